// round 11
// baseline (speedup 1.0000x reference)
#include <cuda_runtime.h>
#include <cuda_fp16.h>
#include <cstdint>
#include <math.h>

// ---------------- problem constants ----------------
#define NN    100000
#define EE    1600000
#define DIN   256
#define DOUT  64
#define KPROP 10
#define ALPHA 0.1f

#define EPMAX (EE + 4 * NN + 16)   // padded edge buffer

// ---------------- static device scratch ----------------
__device__ __half g_hh [(size_t)NN * DOUT];   // h in fp16
__device__ __half g_zhA[(size_t)NN * DOUT];
__device__ __half g_zhB[(size_t)NN * DOUT];
__device__ float  g_dinv[NN];

__device__ int   g_cnt   [NN];
__device__ int   g_cursor[NN];
__device__ int   g_rowstart[NN + 1];   // padded-CSR row starts
__device__ int2  g_epk[EPMAX];         // packed (src idx, weight bits)
__device__ int   g_blksum[128];
__device__ int   g_blkoff[128];

#define SCAN_BS  1024
#define SCAN_NB  ((NN + SCAN_BS - 1) / SCAN_BS)   // 98
__device__ int g_rowtmp[NN];

// ---------------- helpers ----------------
__device__ __forceinline__ uint32_t f2h2(float a, float b) {
    __half2 h = __floats2half2_rn(a, b);
    return *(uint32_t*)&h;
}

__device__ __forceinline__ void mma_16816(float* c, const uint32_t* a,
                                          uint32_t b0, uint32_t b1) {
    asm volatile(
        "mma.sync.aligned.m16n8k16.row.col.f32.f16.f16.f32 "
        "{%0,%1,%2,%3}, {%4,%5,%6,%7}, {%8,%9}, {%0,%1,%2,%3};"
        : "+f"(c[0]), "+f"(c[1]), "+f"(c[2]), "+f"(c[3])
        : "r"(a[0]), "r"(a[1]), "r"(a[2]), "r"(a[3]), "r"(b0), "r"(b1));
}

__device__ __forceinline__ void ldsm_x4(uint32_t* r, uint32_t addr) {
    asm volatile("ldmatrix.sync.aligned.m8n8.x4.shared.b16 {%0,%1,%2,%3}, [%4];"
                 : "=r"(r[0]), "=r"(r[1]), "=r"(r[2]), "=r"(r[3]) : "r"(addr));
}

// ---------------- tensor-core GEMM + bias + ReLU (reg double-buffered) --
#define GROWS 128
#define XPAD  72   // half stride; row pitch 144B

__global__ __launch_bounds__(256) void gemm_relu(
    const float* __restrict__ x, const float* __restrict__ W,
    const float* __restrict__ b)
{
    __shared__ __half xs[GROWS * XPAD];   // 18.4 KB
    __shared__ __half ws[DOUT * XPAD];    //  9.2 KB

    const int tid  = threadIdx.x;
    const int warp = tid >> 5;
    const int lane = tid & 31;
    const int gid  = lane >> 2;     // 0..7
    const int tg   = lane & 3;      // 0..3
    const int row0 = blockIdx.x * GROWS;
    const int wrow = warp * 16;

    const uint32_t xs_base = (uint32_t)__cvta_generic_to_shared(xs);
    const uint32_t ws_base = (uint32_t)__cvta_generic_to_shared(ws);

    // ldmatrix lane->row/col mapping
    const int arow    = wrow + (lane & 15);
    const int acolsel = (lane >> 4) << 3;                       // 0 or 8
    const int browsel = (((lane >> 4) & 1) << 3) + (lane & 7);  // 0..15
    const int bcolsel = ((lane >> 3) & 1) << 3;                 // 0 or 8

    // loader roles
    const int wn  = tid >> 2;              // 0..63
    const int wkq = (tid & 3) * 16;        // halves
    const int xr  = tid >> 1;              // 0..127
    const int xkq = (tid & 1) * 32;        // halves
    const int xgr = row0 + xr;
    const bool xok = (xgr < NN);

    float4 wf[4];
    float4 xf[8];

    // ---- prefetch chunk 0 ----
    {
        const float4* wsrc = (const float4*)(W + (size_t)wn * DIN + wkq);
#pragma unroll
        for (int i = 0; i < 4; i++) wf[i] = wsrc[i];
        if (xok) {
            const float4* xsrc = (const float4*)(x + (size_t)xgr * DIN + xkq);
#pragma unroll
            for (int i = 0; i < 8; i++) xf[i] = xsrc[i];
        }
    }

    float acc[8][4];
#pragma unroll
    for (int nt = 0; nt < 8; nt++)
#pragma unroll
        for (int q = 0; q < 4; q++) acc[nt][q] = 0.f;

    for (int kc = 0; kc < DIN / 64; kc++) {
        // ---- stage prefetched regs -> half smem ----
        {
            uint4* d = (uint4*)&ws[wn * XPAD + wkq];
#pragma unroll
            for (int i = 0; i < 2; i++) {
                float4 v0 = wf[2 * i], v1 = wf[2 * i + 1];
                uint4 u;
                u.x = f2h2(v0.x, v0.y); u.y = f2h2(v0.z, v0.w);
                u.z = f2h2(v1.x, v1.y); u.w = f2h2(v1.z, v1.w);
                d[i] = u;
            }
        }
        {
            uint4* d = (uint4*)&xs[xr * XPAD + xkq];
            if (xok) {
#pragma unroll
                for (int i = 0; i < 4; i++) {
                    float4 v0 = xf[2 * i], v1 = xf[2 * i + 1];
                    uint4 u;
                    u.x = f2h2(v0.x, v0.y); u.y = f2h2(v0.z, v0.w);
                    u.z = f2h2(v1.x, v1.y); u.w = f2h2(v1.z, v1.w);
                    d[i] = u;
                }
            } else {
                uint4 u = make_uint4(0, 0, 0, 0);
#pragma unroll
                for (int i = 0; i < 4; i++) d[i] = u;
            }
        }
        __syncthreads();

        // ---- issue next chunk's global loads (overlap with mma) ----
        if (kc < DIN / 64 - 1) {
            const int k0n = (kc + 1) * 64;
            const float4* wsrc = (const float4*)(W + (size_t)wn * DIN + k0n + wkq);
#pragma unroll
            for (int i = 0; i < 4; i++) wf[i] = wsrc[i];
            if (xok) {
                const float4* xsrc = (const float4*)(x + (size_t)xgr * DIN + k0n + xkq);
#pragma unroll
                for (int i = 0; i < 8; i++) xf[i] = xsrc[i];
            }
        }

        // ---- 4 k-steps of mma, fragments via ldmatrix.x4 ----
#pragma unroll
        for (int ks = 0; ks < 4; ks++) {
            uint32_t a[4];
            ldsm_x4(a, xs_base + (uint32_t)((arow * XPAD + ks * 16 + acolsel) * 2));
#pragma unroll
            for (int p = 0; p < 4; p++) {
                uint32_t bb[4];
                int brow = p * 16 + browsel;
                ldsm_x4(bb, ws_base + (uint32_t)((brow * XPAD + ks * 16 + bcolsel) * 2));
                mma_16816(acc[2 * p],     a, bb[0], bb[1]);
                mma_16816(acc[2 * p + 1], a, bb[2], bb[3]);
            }
        }
        __syncthreads();
    }

    // ---- epilogue: bias + relu -> g_hh and g_zhA (fp16) ----
    int r0 = row0 + wrow + gid;
    int r1 = r0 + 8;
#pragma unroll
    for (int nt = 0; nt < 8; nt++) {
        int cn = nt * 8 + 2 * tg;
        float b0v = b[cn], b1v = b[cn + 1];
        int ci = (cn >> 1);   // half2 column index (0..31)
        if (r0 < NN) {
            __half2 v = __floats2half2_rn(fmaxf(acc[nt][0] + b0v, 0.f),
                                          fmaxf(acc[nt][1] + b1v, 0.f));
            ((__half2*)g_hh )[r0 * 32 + ci] = v;
            ((__half2*)g_zhA)[r0 * 32 + ci] = v;
        }
        if (r1 < NN) {
            __half2 v = __floats2half2_rn(fmaxf(acc[nt][2] + b0v, 0.f),
                                          fmaxf(acc[nt][3] + b1v, 0.f));
            ((__half2*)g_hh )[r1 * 32 + ci] = v;
            ((__half2*)g_zhA)[r1 * 32 + ci] = v;
        }
    }
}

// ---------------- degree count + scan + padded CSR ----------------
__global__ void cnt_init() {
    int i = blockIdx.x * blockDim.x + threadIdx.x;
    if (i < NN) { g_cnt[i] = 0; g_cursor[i] = 0; }
}

__global__ void deg_acc(const int* __restrict__ dst) {
    int e = blockIdx.x * blockDim.x + threadIdx.x;
    if (e < EE) atomicAdd(&g_cnt[dst[e]], 1);
}

// scanA scans PADDED counts ((cnt+3)&~3) and produces dinv from real counts
__global__ __launch_bounds__(256) void scanA() {
    __shared__ int sh[256];
    int tid  = threadIdx.x;
    int base = blockIdx.x * SCAN_BS + tid * 4;
    int v[4];
#pragma unroll
    for (int q = 0; q < 4; q++) {
        int idx = base + q;
        int c = (idx < NN) ? g_cnt[idx] : 0;
        if (idx < NN) g_dinv[idx] = rsqrtf((float)(c + 1));
        v[q] = (idx < NN) ? ((c + 3) & ~3) : 0;
    }
    int tsum = v[0] + v[1] + v[2] + v[3];
    sh[tid] = tsum;
    __syncthreads();
    for (int off = 1; off < 256; off <<= 1) {
        int x = (tid >= off) ? sh[tid - off] : 0;
        __syncthreads();
        sh[tid] += x;
        __syncthreads();
    }
    int run = sh[tid] - tsum;
#pragma unroll
    for (int q = 0; q < 4; q++) {
        int idx = base + q;
        if (idx < NN) g_rowtmp[idx] = run;
        run += v[q];
    }
    if (tid == 255) g_blksum[blockIdx.x] = sh[255];
}

__global__ __launch_bounds__(128) void scanB() {
    __shared__ int sh[128];
    int tid = threadIdx.x;
    int v = (tid < SCAN_NB) ? g_blksum[tid] : 0;
    sh[tid] = v;
    __syncthreads();
    for (int off = 1; off < 128; off <<= 1) {
        int x = (tid >= off) ? sh[tid - off] : 0;
        __syncthreads();
        sh[tid] += x;
        __syncthreads();
    }
    g_blkoff[tid] = sh[tid] - v;
}

__global__ void scanC() {
    int i = blockIdx.x * blockDim.x + threadIdx.x;
    if (i < NN) g_rowstart[i] = g_rowtmp[i] + g_blkoff[i / SCAN_BS];
    if (i == 0) {
        int lastc = (g_cnt[NN - 1] + 3) & ~3;
        g_rowstart[NN] = g_rowtmp[NN - 1] + g_blkoff[(NN - 1) / SCAN_BS] + lastc;
    }
}

__global__ void csr_fill(const int* __restrict__ src, const int* __restrict__ dst) {
    int e = blockIdx.x * blockDim.x + threadIdx.x;
    if (e >= EE) return;
    int d = dst[e];
    int s = src[e];
    int pos = g_rowstart[d] + atomicAdd(&g_cursor[d], 1);
    float w = 0.9f * g_dinv[s] * g_dinv[d];
    g_epk[pos] = make_int2(s, __float_as_int(w));
}

// zero-weight pad entries (slots cnt..cntp-1 of each node's segment)
__global__ void csr_pad() {
    int i = blockIdx.x * blockDim.x + threadIdx.x;
    if (i >= NN) return;
    int c  = g_cnt[i];
    int cp = (c + 3) & ~3;
    int base = g_rowstart[i];
    for (int t = c; t < cp; t++) g_epk[base + t] = make_int2(0, 0);
}

// ---------------- fused APPNP step (padded CSR, unroll 4 + prefetch) ----
#define WPB 8
__global__ __launch_bounds__(WPB * 32) void appnp_step(int in_sel, int out_sel,
                                                       float* __restrict__ ext) {
    int warp = threadIdx.x >> 5;
    int lane = threadIdx.x & 31;
    int node = blockIdx.x * WPB + warp;
    if (node >= NN) return;

    const __half2* zin = (in_sel == 0) ? (const __half2*)g_zhA
                                       : (const __half2*)g_zhB;

    float di = g_dinv[node];
    float sw = 0.9f * di * di;
    int   ri = node * 32 + lane;

    float2 hd = __half22float2(((const __half2*)g_hh)[ri]);
    float2 zd = __half22float2(zin[ri]);
    float accx = ALPHA * hd.x + sw * zd.x;
    float accy = ALPHA * hd.y + sw * zd.y;

    int j  = g_rowstart[node];
    int j1 = g_rowstart[node + 1];   // (j1 - j) % 4 == 0 guaranteed

    if (j < j1) {
        int2 p[4];
#pragma unroll
        for (int q = 0; q < 4; q++) p[q] = g_epk[j + q];

        for (; j < j1; j += 4) {
            // prefetch next block unconditionally (buffer over-allocated)
            int2 pn[4];
#pragma unroll
            for (int q = 0; q < 4; q++) pn[q] = g_epk[j + 4 + q];

            float2 a[4];
#pragma unroll
            for (int q = 0; q < 4; q++) a[q] = __half22float2(zin[p[q].x * 32 + lane]);
#pragma unroll
            for (int q = 0; q < 4; q++) {
                float w = __int_as_float(p[q].y);
                accx += w * a[q].x;
                accy += w * a[q].y;
            }
#pragma unroll
            for (int q = 0; q < 4; q++) p[q] = pn[q];
        }
    }

    if (out_sel == 3) {
        float2 o; o.x = accx; o.y = accy;
        ((float2*)ext)[ri] = o;
    } else {
        __half2* zout = (out_sel == 0) ? (__half2*)g_zhA : (__half2*)g_zhB;
        zout[ri] = __floats2half2_rn(accx, accy);
    }
}

// ---------------- launch ----------------
extern "C" void kernel_launch(void* const* d_in, const int* in_sizes, int n_in,
                              void* d_out, int out_size) {
    const float* x  = (const float*)d_in[0];
    const int*   ei = (const int*)  d_in[1];
    const float* W  = (const float*)d_in[2];
    const float* b  = (const float*)d_in[3];
    float* out = (float*)d_out;

    const int* se = ei;        // src row
    const int* de = ei + EE;   // dst row

    cnt_init<<<(NN + 255) / 256, 256>>>();                       // 0
    deg_acc<<<(EE + 255) / 256, 256>>>(de);                      // 1
    scanA<<<SCAN_NB, 256>>>();                                   // 2 (+dinv)
    gemm_relu<<<(NN + GROWS - 1) / GROWS, 256>>>(x, W, b);       // 3  <- profiled
    scanB<<<1, 128>>>();                                         // 4
    scanC<<<(NN + 255) / 256, 256>>>();                          // 5
    csr_fill<<<(EE + 255) / 256, 256>>>(se, de);                 // 6
    csr_pad<<<(NN + 255) / 256, 256>>>();                        // 7

    // K-step APPNP propagation; state ping-pongs A<->B; last step -> d_out fp32
    const int step_grid = (NN + WPB - 1) / WPB;
    for (int k = 0; k < KPROP; k++) {
        int in_sel  = k & 1;                       // 0=A, 1=B
        int out_sel = (k == KPROP - 1) ? 3 : 1 - (k & 1);
        appnp_step<<<step_grid, WPB * 32>>>(in_sel, out_sel, out);
    }
}

// round 12
// speedup vs baseline: 1.0542x; 1.0542x over previous
#include <cuda_runtime.h>
#include <cuda_fp16.h>
#include <cstdint>
#include <math.h>

// ---------------- problem constants ----------------
#define NN    100000
#define EE    1600000
#define DIN   256
#define DOUT  64
#define KPROP 10
#define ALPHA 0.1f

// ---------------- static device scratch ----------------
__device__ __half g_hh [(size_t)NN * DOUT];   // h in fp16
__device__ __half g_zhA[(size_t)NN * DOUT];
__device__ __half g_zhB[(size_t)NN * DOUT];
__device__ float  g_dinv[NN];

__device__ int   g_cnt   [NN];
__device__ int   g_cursor[NN];
__device__ int   g_rowstart[NN + 1];
__device__ int2  g_epk[EE + 16];     // packed (src idx, weight bits)
__device__ int   g_blksum[128];
__device__ int   g_blkoff[128];

#define SCAN_BS  1024
#define SCAN_NB  ((NN + SCAN_BS - 1) / SCAN_BS)   // 98
__device__ int g_rowtmp[NN];

// ---------------- helpers ----------------
__device__ __forceinline__ uint32_t f2h2(float a, float b) {
    __half2 h = __floats2half2_rn(a, b);
    return *(uint32_t*)&h;
}

__device__ __forceinline__ void mma_16816(float* c, const uint32_t* a,
                                          uint32_t b0, uint32_t b1) {
    asm volatile(
        "mma.sync.aligned.m16n8k16.row.col.f32.f16.f16.f32 "
        "{%0,%1,%2,%3}, {%4,%5,%6,%7}, {%8,%9}, {%0,%1,%2,%3};"
        : "+f"(c[0]), "+f"(c[1]), "+f"(c[2]), "+f"(c[3])
        : "r"(a[0]), "r"(a[1]), "r"(a[2]), "r"(a[3]), "r"(b0), "r"(b1));
}

__device__ __forceinline__ void ldsm_x4(uint32_t* r, uint32_t addr) {
    asm volatile("ldmatrix.sync.aligned.m8n8.x4.shared.b16 {%0,%1,%2,%3}, [%4];"
                 : "=r"(r[0]), "=r"(r[1]), "=r"(r[2]), "=r"(r[3]) : "r"(addr));
}

// ---------------- tensor-core GEMM + bias + ReLU (R8-proven version) ----
#define GROWS 128
#define XPAD  72   // half stride; row pitch 144B

__global__ __launch_bounds__(256) void gemm_relu(
    const float* __restrict__ x, const float* __restrict__ W,
    const float* __restrict__ b)
{
    __shared__ __half xs[GROWS * XPAD];   // 18.4 KB
    __shared__ __half ws[DOUT * XPAD];    //  9.2 KB

    const int tid  = threadIdx.x;
    const int warp = tid >> 5;
    const int lane = tid & 31;
    const int gid  = lane >> 2;     // 0..7
    const int tg   = lane & 3;      // 0..3
    const int row0 = blockIdx.x * GROWS;
    const int wrow = warp * 16;

    const uint32_t xs_base = (uint32_t)__cvta_generic_to_shared(xs);
    const uint32_t ws_base = (uint32_t)__cvta_generic_to_shared(ws);

    // ldmatrix lane->row/col mapping
    const int arow    = wrow + (lane & 15);
    const int acolsel = (lane >> 4) << 3;                       // 0 or 8
    const int browsel = (((lane >> 4) & 1) << 3) + (lane & 7);  // 0..15
    const int bcolsel = ((lane >> 3) & 1) << 3;                 // 0 or 8

    float acc[8][4];
#pragma unroll
    for (int nt = 0; nt < 8; nt++)
#pragma unroll
        for (int q = 0; q < 4; q++) acc[nt][q] = 0.f;

    for (int kc = 0; kc < DIN / 64; kc++) {
        const int k0 = kc * 64;
        __syncthreads();
        // ---- W chunk [64 n][64 k] fp32 -> half smem (uint4 stores) ----
        {
            int n  = tid >> 2;             // 0..63
            int kq = (tid & 3) * 16;       // halves
            const float4* wsrc = (const float4*)(W + (size_t)n * DIN + k0 + kq);
            uint4* d = (uint4*)&ws[n * XPAD + kq];
#pragma unroll
            for (int i = 0; i < 2; i++) {
                float4 v0 = wsrc[2 * i], v1 = wsrc[2 * i + 1];
                uint4 u;
                u.x = f2h2(v0.x, v0.y); u.y = f2h2(v0.z, v0.w);
                u.z = f2h2(v1.x, v1.y); u.w = f2h2(v1.z, v1.w);
                d[i] = u;
            }
        }
        // ---- x chunk [128 r][64 k] fp32 -> half smem (uint4 stores) ----
        {
            int r  = tid >> 1;             // 0..127
            int kq = (tid & 1) * 32;       // halves
            int gr = row0 + r;
            uint4* d = (uint4*)&xs[r * XPAD + kq];
            if (gr < NN) {
                const float4* xsrc = (const float4*)(x + (size_t)gr * DIN + k0 + kq);
#pragma unroll
                for (int i = 0; i < 4; i++) {
                    float4 v0 = xsrc[2 * i], v1 = xsrc[2 * i + 1];
                    uint4 u;
                    u.x = f2h2(v0.x, v0.y); u.y = f2h2(v0.z, v0.w);
                    u.z = f2h2(v1.x, v1.y); u.w = f2h2(v1.z, v1.w);
                    d[i] = u;
                }
            } else {
                uint4 u = make_uint4(0, 0, 0, 0);
#pragma unroll
                for (int i = 0; i < 4; i++) d[i] = u;
            }
        }
        __syncthreads();

        // ---- 4 k-steps of mma, fragments via ldmatrix.x4 ----
#pragma unroll
        for (int ks = 0; ks < 4; ks++) {
            uint32_t a[4];
            ldsm_x4(a, xs_base + (uint32_t)((arow * XPAD + ks * 16 + acolsel) * 2));
#pragma unroll
            for (int p = 0; p < 4; p++) {
                uint32_t bb[4];
                int brow = p * 16 + browsel;
                ldsm_x4(bb, ws_base + (uint32_t)((brow * XPAD + ks * 16 + bcolsel) * 2));
                mma_16816(acc[2 * p],     a, bb[0], bb[1]);
                mma_16816(acc[2 * p + 1], a, bb[2], bb[3]);
            }
        }
    }

    // ---- epilogue: bias + relu -> g_hh and g_zhA (fp16) ----
    int r0 = row0 + wrow + gid;
    int r1 = r0 + 8;
#pragma unroll
    for (int nt = 0; nt < 8; nt++) {
        int cn = nt * 8 + 2 * tg;
        float b0v = b[cn], b1v = b[cn + 1];
        int ci = (cn >> 1);   // half2 column index (0..31)
        if (r0 < NN) {
            __half2 v = __floats2half2_rn(fmaxf(acc[nt][0] + b0v, 0.f),
                                          fmaxf(acc[nt][1] + b1v, 0.f));
            ((__half2*)g_hh )[r0 * 32 + ci] = v;
            ((__half2*)g_zhA)[r0 * 32 + ci] = v;
        }
        if (r1 < NN) {
            __half2 v = __floats2half2_rn(fmaxf(acc[nt][2] + b0v, 0.f),
                                          fmaxf(acc[nt][3] + b1v, 0.f));
            ((__half2*)g_hh )[r1 * 32 + ci] = v;
            ((__half2*)g_zhA)[r1 * 32 + ci] = v;
        }
    }
}

// ---------------- degree count + scan + CSR ----------------
__global__ void cnt_init() {
    int i = blockIdx.x * blockDim.x + threadIdx.x;
    if (i < NN) { g_cnt[i] = 0; g_cursor[i] = 0; }
}

__global__ void deg_acc(const int* __restrict__ dst) {
    int e = blockIdx.x * blockDim.x + threadIdx.x;
    if (e < EE) atomicAdd(&g_cnt[dst[e]], 1);
}

// scanA also produces dinv (fused make_dinv)
__global__ __launch_bounds__(256) void scanA() {
    __shared__ int sh[256];
    int tid  = threadIdx.x;
    int base = blockIdx.x * SCAN_BS + tid * 4;
    int v[4];
#pragma unroll
    for (int q = 0; q < 4; q++) {
        int idx = base + q;
        v[q] = (idx < NN) ? g_cnt[idx] : 0;
        if (idx < NN) g_dinv[idx] = rsqrtf((float)(v[q] + 1));
    }
    int tsum = v[0] + v[1] + v[2] + v[3];
    sh[tid] = tsum;
    __syncthreads();
    for (int off = 1; off < 256; off <<= 1) {
        int x = (tid >= off) ? sh[tid - off] : 0;
        __syncthreads();
        sh[tid] += x;
        __syncthreads();
    }
    int run = sh[tid] - tsum;
#pragma unroll
    for (int q = 0; q < 4; q++) {
        int idx = base + q;
        if (idx < NN) g_rowtmp[idx] = run;
        run += v[q];
    }
    if (tid == 255) g_blksum[blockIdx.x] = sh[255];
}

__global__ __launch_bounds__(128) void scanB() {
    __shared__ int sh[128];
    int tid = threadIdx.x;
    int v = (tid < SCAN_NB) ? g_blksum[tid] : 0;
    sh[tid] = v;
    __syncthreads();
    for (int off = 1; off < 128; off <<= 1) {
        int x = (tid >= off) ? sh[tid - off] : 0;
        __syncthreads();
        sh[tid] += x;
        __syncthreads();
    }
    g_blkoff[tid] = sh[tid] - v;
}

__global__ void scanC() {
    int i = blockIdx.x * blockDim.x + threadIdx.x;
    if (i < NN) g_rowstart[i] = g_rowtmp[i] + g_blkoff[i / SCAN_BS];
    if (i == 0) g_rowstart[NN] = EE;
}

__global__ void csr_fill(const int* __restrict__ src, const int* __restrict__ dst) {
    int e = blockIdx.x * blockDim.x + threadIdx.x;
    if (e >= EE) return;
    int d = dst[e];
    int s = src[e];
    int pos = g_rowstart[d] + atomicAdd(&g_cursor[d], 1);
    float w = 0.9f * g_dinv[s] * g_dinv[d];
    g_epk[pos] = make_int2(s, __float_as_int(w));
}

// ---------------- fused APPNP step (pull, half z, packed edges) --------
#define WPB 8
__global__ __launch_bounds__(WPB * 32) void appnp_step(int in_sel, int out_sel,
                                                       float* __restrict__ ext) {
    int warp = threadIdx.x >> 5;
    int lane = threadIdx.x & 31;
    int node = blockIdx.x * WPB + warp;
    if (node >= NN) return;

    const __half2* zin = (in_sel == 0) ? (const __half2*)g_zhA
                                       : (const __half2*)g_zhB;

    float di = g_dinv[node];
    float sw = 0.9f * di * di;
    int   ri = node * 32 + lane;

    float2 hd = __half22float2(((const __half2*)g_hh)[ri]);
    float2 zd = __half22float2(zin[ri]);
    float accx = ALPHA * hd.x + sw * zd.x;
    float accy = ALPHA * hd.y + sw * zd.y;

    int j  = g_rowstart[node];
    int j1 = g_rowstart[node + 1];

    for (; j + 8 <= j1; j += 8) {
        int2 p[8];
#pragma unroll
        for (int q = 0; q < 8; q++) p[q] = g_epk[j + q];
        float2 a[8];
#pragma unroll
        for (int q = 0; q < 8; q++) a[q] = __half22float2(zin[p[q].x * 32 + lane]);
#pragma unroll
        for (int q = 0; q < 8; q++) {
            float w = __int_as_float(p[q].y);
            accx += w * a[q].x;
            accy += w * a[q].y;
        }
    }
    for (; j < j1; j++) {
        int2  p = g_epk[j];
        float w = __int_as_float(p.y);
        float2 a = __half22float2(zin[p.x * 32 + lane]);
        accx += w * a.x;
        accy += w * a.y;
    }

    if (out_sel == 3) {
        float2 o; o.x = accx; o.y = accy;
        ((float2*)ext)[ri] = o;
    } else {
        __half2* zout = (out_sel == 0) ? (__half2*)g_zhA : (__half2*)g_zhB;
        zout[ri] = __floats2half2_rn(accx, accy);
    }
}

// ---------------- launch (forked graph: GEMM || CSR build) -------------
extern "C" void kernel_launch(void* const* d_in, const int* in_sizes, int n_in,
                              void* d_out, int out_size) {
    const float* x  = (const float*)d_in[0];
    const int*   ei = (const int*)  d_in[1];
    const float* W  = (const float*)d_in[2];
    const float* b  = (const float*)d_in[3];
    float* out = (float*)d_out;

    const int* se = ei;        // src row
    const int* de = ei + EE;   // dst row

    // side stream + events, created once on the first (uncaptured) call
    static cudaStream_t s2 = nullptr;
    static cudaEvent_t  evFork = nullptr, evJoin = nullptr;
    if (s2 == nullptr) {
        cudaStreamCreateWithFlags(&s2, cudaStreamNonBlocking);
        cudaEventCreateWithFlags(&evFork, cudaEventDisableTiming);
        cudaEventCreateWithFlags(&evJoin, cudaEventDisableTiming);
    }

    // fork: GEMM runs on s2, concurrent with the CSR build chain
    cudaEventRecord(evFork, 0);
    cudaStreamWaitEvent(s2, evFork, 0);
    gemm_relu<<<(NN + GROWS - 1) / GROWS, 256, 0, s2>>>(x, W, b);
    cudaEventRecord(evJoin, s2);

    // origin stream: degree + scan + CSR build
    cnt_init<<<(NN + 255) / 256, 256>>>();
    deg_acc<<<(EE + 255) / 256, 256>>>(de);
    scanA<<<SCAN_NB, 256>>>();
    scanB<<<1, 128>>>();
    scanC<<<(NN + 255) / 256, 256>>>();
    csr_fill<<<(EE + 255) / 256, 256>>>(se, de);

    // join: steps need both GEMM outputs and the CSR
    cudaStreamWaitEvent(0, evJoin, 0);

    // K-step APPNP propagation; state ping-pongs A<->B; last step -> d_out fp32
    const int step_grid = (NN + WPB - 1) / WPB;
    for (int k = 0; k < KPROP; k++) {
        int in_sel  = k & 1;                       // 0=A, 1=B
        int out_sel = (k == KPROP - 1) ? 3 : 1 - (k & 1);
        appnp_step<<<step_grid, WPB * 32>>>(in_sel, out_sel, out);
    }
}